// round 6
// baseline (speedup 1.0000x reference)
#include <cuda_runtime.h>

#define HH 512
#define WW 512
#define TPB 128           // 128 threads * 4 cols = 512 = WW
#define NBLK 1824         // 152 SMs * 12 blocks/SM worth of slices
#define EPS 1e-6f

// scratch for per-block partial sums + completion ticket (no cudaMalloc allowed)
__device__ float g_partials[NBLK];
__device__ unsigned int g_ticket;   // zero-init; last block resets it to 0

__device__ __forceinline__ float4 ld4(const float* __restrict__ p) {
    return *reinterpret_cast<const float4*>(p);
}

// single-MUFU approximate sqrt (max rel err ~1e-7, far below 1e-3 tolerance)
__device__ __forceinline__ float fsqrt_ap(float x) {
    float r;
    asm("sqrt.approx.f32 %0, %1;" : "=f"(r) : "f"(x));
    return r;
}

__global__ __launch_bounds__(TPB, 10)   // allow 48 regs; 10 blocks/SM (62.5% occ)
void grad_loss_kernel(const float* __restrict__ in, const float* __restrict__ tg,
                      float* __restrict__ out, int total_rows, float inv_n) {
    const int t    = threadIdx.x;
    const int lane = t & 31;
    const int w0   = t * 4;
    const bool hasL = (w0 > 0);
    const bool hasR = (w0 + 4 < WW);

    // even split of the flattened row space [0, total_rows)
    const int nb   = gridDim.x;
    const int base = total_rows / nb;
    const int rem  = total_rows % nb;
    const int bid  = blockIdx.x;
    const int rs   = bid * base + min(bid, rem);
    const int re   = rs + base + (bid < rem ? 1 : 0);

    // pi/pt point at the CURRENT row rg
    const float* pi = in + (size_t)rs * WW + w0;
    const float* pt = tg + (size_t)rs * WW + w0;

    const float4 z4 = make_float4(0.f, 0.f, 0.f, 0.f);
    float sum = 0.f;

    // 4 rotating slots per array: roles (u=rg-1, c=rg, n=rg+1, p=prefetch rg+2).
    // Planes are contiguous, so neighbor rows are always valid global rows;
    // plane edges are handled by MASKING u/n to zero at compute time.
    float4 Xi, Yi, Zi, Wi, Xt, Yt, Zt, Wt;

    Xi = (rs > 0) ? ld4(pi - WW) : z4;                    // row rs-1
    Xt = (rs > 0) ? ld4(pt - WW) : z4;
    Yi = ld4(pi);  Yt = ld4(pt);                          // row rs
    Zi = (rs + 1 < total_rows) ? ld4(pi + WW) : z4;       // row rs+1
    Zt = (rs + 1 < total_rows) ? ld4(pt + WW) : z4;

    // one pipelined step: prefetch row rg+2 into p, compute row rg from u,c,n
    auto step = [&](float4& u_i, float4& c_i, float4& n_i, float4& p_i,
                    float4& u_t, float4& c_t, float4& n_t, float4& p_t, int rg) {
        // ---- prefetch (consumed 2 iterations from now) ----
        if (rg + 2 < total_rows) {
            p_i = ld4(pi + 2 * WW);
            p_t = ld4(pt + 2 * WW);
        } else {
            p_i = z4; p_t = z4;
        }

        const int r = rg & (HH - 1);
        // plane-edge masks: u slot is dead after this step -> overwrite;
        // n slot must survive (becomes c) -> masked temps
        if (r == 0) { u_i = z4; u_t = z4; }
        const float4 nn_i = (r == HH - 1) ? z4 : n_i;
        const float4 nn_t = (r == HH - 1) ? z4 : n_t;

        // horizontal neighbors via warp shuffle; warp-edge lanes use a
        // single-lane predicated load
        float lci = __shfl_up_sync(0xffffffffu, c_i.w, 1);
        float lct = __shfl_up_sync(0xffffffffu, c_t.w, 1);
        float rci = __shfl_down_sync(0xffffffffu, c_i.x, 1);
        float rct = __shfl_down_sync(0xffffffffu, c_t.x, 1);
        if (lane == 0)  { lci = hasL ? pi[-1] : 0.f; lct = hasL ? pt[-1] : 0.f; }
        if (lane == 31) { rci = hasR ? pi[4]  : 0.f; rct = hasR ? pt[4]  : 0.f; }

        float gv, gh, a, b;

        gv = nn_i.x - u_i.x; gh = c_i.y - lci;
        a  = fsqrt_ap(fmaf(gv, gv, fmaf(gh, gh, EPS)));
        gv = nn_t.x - u_t.x; gh = c_t.y - lct;
        b  = fsqrt_ap(fmaf(gv, gv, fmaf(gh, gh, EPS)));
        sum += fabsf(a - b);

        gv = nn_i.y - u_i.y; gh = c_i.z - c_i.x;
        a  = fsqrt_ap(fmaf(gv, gv, fmaf(gh, gh, EPS)));
        gv = nn_t.y - u_t.y; gh = c_t.z - c_t.x;
        b  = fsqrt_ap(fmaf(gv, gv, fmaf(gh, gh, EPS)));
        sum += fabsf(a - b);

        gv = nn_i.z - u_i.z; gh = c_i.w - c_i.y;
        a  = fsqrt_ap(fmaf(gv, gv, fmaf(gh, gh, EPS)));
        gv = nn_t.z - u_t.z; gh = c_t.w - c_t.y;
        b  = fsqrt_ap(fmaf(gv, gv, fmaf(gh, gh, EPS)));
        sum += fabsf(a - b);

        gv = nn_i.w - u_i.w; gh = rci - c_i.z;
        a  = fsqrt_ap(fmaf(gv, gv, fmaf(gh, gh, EPS)));
        gv = nn_t.w - u_t.w; gh = rct - c_t.z;
        b  = fsqrt_ap(fmaf(gv, gv, fmaf(gh, gh, EPS)));
        sum += fabsf(a - b);

        pi += WW; pt += WW;
    };

    int rg = rs;
    for (; rg + 4 <= re; rg += 4) {
        step(Xi, Yi, Zi, Wi, Xt, Yt, Zt, Wt, rg);
        step(Yi, Zi, Wi, Xi, Yt, Zt, Wt, Xt, rg + 1);
        step(Zi, Wi, Xi, Yi, Zt, Wt, Xt, Yt, rg + 2);
        step(Wi, Xi, Yi, Zi, Wt, Xt, Yt, Zt, rg + 3);
    }
    if (rg < re) { step(Xi, Yi, Zi, Wi, Xt, Yt, Zt, Wt, rg); ++rg; }
    if (rg < re) { step(Yi, Zi, Wi, Xi, Yt, Zt, Wt, Xt, rg); ++rg; }
    if (rg < re) { step(Zi, Wi, Xi, Yi, Zt, Wt, Xt, Yt, rg); ++rg; }

    // block reduction: warp shfl, then across 4 warps via smem
    #pragma unroll
    for (int o = 16; o > 0; o >>= 1)
        sum += __shfl_down_sync(0xffffffffu, sum, o);

    __shared__ float ws[TPB / 32];
    __shared__ bool is_last;
    if ((t & 31) == 0) ws[t >> 5] = sum;
    __syncthreads();

    if (t == 0) {
        float s = ws[0] + ws[1] + ws[2] + ws[3];
        g_partials[bid] = s;
        __threadfence();                               // partial visible before ticket
        unsigned done = atomicAdd(&g_ticket, 1u);
        is_last = (done == (unsigned)(nb - 1));
    }
    __syncthreads();

    if (is_last) {
        const volatile float* vp = (const volatile float*)g_partials;
        float s = 0.f;
        for (int i = t; i < nb; i += TPB)
            s += vp[i];

        #pragma unroll
        for (int o = 16; o > 0; o >>= 1)
            s += __shfl_down_sync(0xffffffffu, s, o);

        if ((t & 31) == 0) ws[t >> 5] = s;
        __syncthreads();
        if (t == 0) {
            out[0] = (ws[0] + ws[1] + ws[2] + ws[3]) * inv_n;
            g_ticket = 0;                              // reset for next graph replay
        }
    }
}

extern "C" void kernel_launch(void* const* d_in, const int* in_sizes, int n_in,
                              void* d_out, int out_size) {
    const float* in = (const float*)d_in[0];
    const float* tg = (const float*)d_in[1];
    float* out = (float*)d_out;

    const int total = in_sizes[0];                 // 32*3*512*512
    const int total_rows = total / WW;             // 49152

    grad_loss_kernel<<<NBLK, TPB>>>(in, tg, out, total_rows, 1.0f / (float)total);
}

// round 7
// speedup vs baseline: 1.2250x; 1.2250x over previous
#include <cuda_runtime.h>

#define HH 512
#define WW 512
#define TPB 128           // 128 threads * 4 cols = 512 = WW
#define NBLK 1520         // 152 SMs * 10 blocks/SM == occupancy cap (ONE full wave)
#define EPS 1e-6f

// scratch for per-block partial sums + completion ticket (no cudaMalloc allowed)
__device__ float g_partials[NBLK];
__device__ unsigned int g_ticket;   // zero-init; last block resets it to 0

__device__ __forceinline__ float4 ld4(const float* __restrict__ p) {
    return *reinterpret_cast<const float4*>(p);
}

// single-MUFU approximate sqrt (max rel err ~1e-7, far below 1e-3 tolerance)
__device__ __forceinline__ float fsqrt_ap(float x) {
    float r;
    asm("sqrt.approx.f32 %0, %1;" : "=f"(r) : "f"(x));
    return r;
}

__global__ __launch_bounds__(TPB, 10)   // 48 regs allowed; 10 blocks/SM
void grad_loss_kernel(const float* __restrict__ in, const float* __restrict__ tg,
                      float* __restrict__ out, int total_rows, float inv_n) {
    const int t    = threadIdx.x;
    const int lane = t & 31;
    const int w0   = t * 4;
    const bool hasL = (w0 > 0);
    const bool hasR = (w0 + 4 < WW);

    // even split of the flattened row space [0, total_rows)
    const int nb   = gridDim.x;
    const int base = total_rows / nb;
    const int rem  = total_rows % nb;
    const int bid  = blockIdx.x;
    const int rs   = bid * base + min(bid, rem);
    const int re   = rs + base + (bid < rem ? 1 : 0);

    // pi/pt point at the CURRENT row rg
    const float* pi = in + (size_t)rs * WW + w0;
    const float* pt = tg + (size_t)rs * WW + w0;

    const float4 z4 = make_float4(0.f, 0.f, 0.f, 0.f);
    float sum = 0.f;

    // 4 rotating slots per array: roles (u=rg-1, c=rg, n=rg+1, p=prefetch rg+2).
    // Planes are contiguous, so neighbor rows are always valid global rows;
    // plane edges are handled by MASKING u/n to zero at compute time.
    float4 Xi, Yi, Zi, Wi, Xt, Yt, Zt, Wt;

    Xi = (rs > 0) ? ld4(pi - WW) : z4;                    // row rs-1
    Xt = (rs > 0) ? ld4(pt - WW) : z4;
    Yi = ld4(pi);  Yt = ld4(pt);                          // row rs
    Zi = (rs + 1 < total_rows) ? ld4(pi + WW) : z4;       // row rs+1
    Zt = (rs + 1 < total_rows) ? ld4(pt + WW) : z4;

    // one pipelined step: prefetch row rg+2 into p, compute row rg from u,c,n
    auto step = [&](float4& u_i, float4& c_i, float4& n_i, float4& p_i,
                    float4& u_t, float4& c_t, float4& n_t, float4& p_t, int rg) {
        // ---- prefetch (consumed 2 iterations from now) ----
        if (rg + 2 < total_rows) {
            p_i = ld4(pi + 2 * WW);
            p_t = ld4(pt + 2 * WW);
        } else {
            p_i = z4; p_t = z4;
        }

        const int r = rg & (HH - 1);
        // plane-edge masks: u slot is dead after this step -> overwrite;
        // n slot must survive (becomes c) -> masked temps
        if (r == 0) { u_i = z4; u_t = z4; }
        const float4 nn_i = (r == HH - 1) ? z4 : n_i;
        const float4 nn_t = (r == HH - 1) ? z4 : n_t;

        // horizontal neighbors via warp shuffle; warp-edge lanes use a
        // single-lane predicated load
        float lci = __shfl_up_sync(0xffffffffu, c_i.w, 1);
        float lct = __shfl_up_sync(0xffffffffu, c_t.w, 1);
        float rci = __shfl_down_sync(0xffffffffu, c_i.x, 1);
        float rct = __shfl_down_sync(0xffffffffu, c_t.x, 1);
        if (lane == 0)  { lci = hasL ? pi[-1] : 0.f; lct = hasL ? pt[-1] : 0.f; }
        if (lane == 31) { rci = hasR ? pi[4]  : 0.f; rct = hasR ? pt[4]  : 0.f; }

        float gv, gh, a, b;

        gv = nn_i.x - u_i.x; gh = c_i.y - lci;
        a  = fsqrt_ap(fmaf(gv, gv, fmaf(gh, gh, EPS)));
        gv = nn_t.x - u_t.x; gh = c_t.y - lct;
        b  = fsqrt_ap(fmaf(gv, gv, fmaf(gh, gh, EPS)));
        sum += fabsf(a - b);

        gv = nn_i.y - u_i.y; gh = c_i.z - c_i.x;
        a  = fsqrt_ap(fmaf(gv, gv, fmaf(gh, gh, EPS)));
        gv = nn_t.y - u_t.y; gh = c_t.z - c_t.x;
        b  = fsqrt_ap(fmaf(gv, gv, fmaf(gh, gh, EPS)));
        sum += fabsf(a - b);

        gv = nn_i.z - u_i.z; gh = c_i.w - c_i.y;
        a  = fsqrt_ap(fmaf(gv, gv, fmaf(gh, gh, EPS)));
        gv = nn_t.z - u_t.z; gh = c_t.w - c_t.y;
        b  = fsqrt_ap(fmaf(gv, gv, fmaf(gh, gh, EPS)));
        sum += fabsf(a - b);

        gv = nn_i.w - u_i.w; gh = rci - c_i.z;
        a  = fsqrt_ap(fmaf(gv, gv, fmaf(gh, gh, EPS)));
        gv = nn_t.w - u_t.w; gh = rct - c_t.z;
        b  = fsqrt_ap(fmaf(gv, gv, fmaf(gh, gh, EPS)));
        sum += fabsf(a - b);

        pi += WW; pt += WW;
    };

    int rg = rs;
    for (; rg + 4 <= re; rg += 4) {
        step(Xi, Yi, Zi, Wi, Xt, Yt, Zt, Wt, rg);
        step(Yi, Zi, Wi, Xi, Yt, Zt, Wt, Xt, rg + 1);
        step(Zi, Wi, Xi, Yi, Zt, Wt, Xt, Yt, rg + 2);
        step(Wi, Xi, Yi, Zi, Wt, Xt, Yt, Zt, rg + 3);
    }
    if (rg < re) { step(Xi, Yi, Zi, Wi, Xt, Yt, Zt, Wt, rg); ++rg; }
    if (rg < re) { step(Yi, Zi, Wi, Xi, Yt, Zt, Wt, Xt, rg); ++rg; }
    if (rg < re) { step(Zi, Wi, Xi, Yi, Zt, Wt, Xt, Yt, rg); ++rg; }

    // block reduction: warp shfl, then across 4 warps via smem
    #pragma unroll
    for (int o = 16; o > 0; o >>= 1)
        sum += __shfl_down_sync(0xffffffffu, sum, o);

    __shared__ float ws[TPB / 32];
    __shared__ bool is_last;
    if ((t & 31) == 0) ws[t >> 5] = sum;
    __syncthreads();

    if (t == 0) {
        float s = ws[0] + ws[1] + ws[2] + ws[3];
        g_partials[bid] = s;
        __threadfence();                               // partial visible before ticket
        unsigned done = atomicAdd(&g_ticket, 1u);
        is_last = (done == (unsigned)(nb - 1));
    }
    __syncthreads();

    if (is_last) {
        const volatile float* vp = (const volatile float*)g_partials;
        float s = 0.f;
        for (int i = t; i < nb; i += TPB)
            s += vp[i];

        #pragma unroll
        for (int o = 16; o > 0; o >>= 1)
            s += __shfl_down_sync(0xffffffffu, s, o);

        if ((t & 31) == 0) ws[t >> 5] = s;
        __syncthreads();
        if (t == 0) {
            out[0] = (ws[0] + ws[1] + ws[2] + ws[3]) * inv_n;
            g_ticket = 0;                              // reset for next graph replay
        }
    }
}

extern "C" void kernel_launch(void* const* d_in, const int* in_sizes, int n_in,
                              void* d_out, int out_size) {
    const float* in = (const float*)d_in[0];
    const float* tg = (const float*)d_in[1];
    float* out = (float*)d_out;

    const int total = in_sizes[0];                 // 32*3*512*512
    const int total_rows = total / WW;             // 49152

    grad_loss_kernel<<<NBLK, TPB>>>(in, tg, out, total_rows, 1.0f / (float)total);
}